// round 15
// baseline (speedup 1.0000x reference)
#include <cuda_runtime.h>
#include <cuda_bf16.h>
#include <stdint.h>
#include <math.h>

#define D_MODEL 2048
#define NH      16
#define NKV     4
#define DH      128
#define D1      64
#define D2      64
#define T_SEQ   2048
#define B_SZ    2
#define BT      (B_SZ * T_SEQ)          // 4096
#define WSIZE   1024
#define QKV_N   ((NH + NKV) * DH)       // 2560
#define QKV_P   2688                    // padded: qkv (2560) + rk (64) + zero pad (64)

// ---------------- scratch (device globals; no runtime allocation) ----------------
// split-bf16 Q/K/V
__device__ __nv_bfloat16 g_Qh[B_SZ * NH  * T_SEQ * DH];
__device__ __nv_bfloat16 g_Ql[B_SZ * NH  * T_SEQ * DH];
__device__ __nv_bfloat16 g_Kh[B_SZ * NKV * T_SEQ * DH];
__device__ __nv_bfloat16 g_Kl[B_SZ * NKV * T_SEQ * DH];
__device__ __nv_bfloat16 g_Vh[B_SZ * NKV * T_SEQ * DH];
__device__ __nv_bfloat16 g_Vl[B_SZ * NKV * T_SEQ * DH];

// split-bf16 GEMM operand copies
__device__ __nv_bfloat16 g_Ah [BT * D_MODEL];
__device__ __nv_bfloat16 g_Al [BT * D_MODEL];
__device__ __nv_bfloat16 g_Bqh[D_MODEL * QKV_P];     // pad cols stay zero (BSS init)
__device__ __nv_bfloat16 g_Bql[D_MODEL * QKV_P];
__device__ __nv_bfloat16 g_Bgh[D_MODEL * D_MODEL];
__device__ __nv_bfloat16 g_Bgl[D_MODEL * D_MODEL];

// ---------------- fp32 -> (hi, lo) bf16 split ----------------
__global__ void cvt_split(const float* __restrict__ src, __nv_bfloat16* __restrict__ hi,
                          __nv_bfloat16* __restrict__ lo, int n) {
    int i = blockIdx.x * 256 + threadIdx.x;
    if (i < n) {
        float f = src[i];
        __nv_bfloat16 h = __float2bfloat16(f);
        hi[i] = h;
        lo[i] = __float2bfloat16(f - __bfloat162float(h));
    }
}

// fp32 [rows, scols] -> split bf16 written into [rows, dcols] at column offset coff
__global__ void cvt_split_pad(const float* __restrict__ src, __nv_bfloat16* __restrict__ hi,
                              __nv_bfloat16* __restrict__ lo, int rows, int scols,
                              int dcols, int coff) {
    int i = blockIdx.x * 256 + threadIdx.x;
    if (i < rows * scols) {
        int r = i / scols;
        int c = i % scols;
        float f = src[i];
        __nv_bfloat16 h = __float2bfloat16(f);
        size_t o = (size_t)r * dcols + coff + c;
        hi[o] = h;
        lo[o] = __float2bfloat16(f - __bfloat162float(h));
    }
}

// ---------------- mma / ldmatrix / cp.async helpers ----------------
__device__ __forceinline__ void ldsm_x4(uint32_t* r, unsigned addr) {
    asm volatile("ldmatrix.sync.aligned.m8n8.x4.shared.b16 {%0,%1,%2,%3}, [%4];"
        : "=r"(r[0]), "=r"(r[1]), "=r"(r[2]), "=r"(r[3]) : "r"(addr));
}
__device__ __forceinline__ void ldsm_x4_t(uint32_t* r, unsigned addr) {
    asm volatile("ldmatrix.sync.aligned.m8n8.x4.trans.shared.b16 {%0,%1,%2,%3}, [%4];"
        : "=r"(r[0]), "=r"(r[1]), "=r"(r[2]), "=r"(r[3]) : "r"(addr));
}
__device__ __forceinline__ void mma_bf16(float* d, const uint32_t* a, const uint32_t* b) {
    asm volatile("mma.sync.aligned.m16n8k16.row.col.f32.bf16.bf16.f32 "
        "{%0,%1,%2,%3}, {%4,%5,%6,%7}, {%8,%9}, {%0,%1,%2,%3};"
        : "+f"(d[0]), "+f"(d[1]), "+f"(d[2]), "+f"(d[3])
        : "r"(a[0]), "r"(a[1]), "r"(a[2]), "r"(a[3]), "r"(b[0]), "r"(b[1]));
}
__device__ __forceinline__ uint32_t pack_bf16x2(float x, float y) {
    __nv_bfloat162 t = __floats2bfloat162_rn(x, y);
    return *(uint32_t*)&t;
}
__device__ __forceinline__ void cp16(unsigned saddr, const void* gptr) {
    asm volatile("cp.async.cg.shared.global [%0], [%1], 16;" :: "r"(saddr), "l"(gptr));
}
__device__ __forceinline__ void cp_commit() {
    asm volatile("cp.async.commit_group;");
}
__device__ __forceinline__ void cp_wait0() {
    asm volatile("cp.async.wait_group 0;");
}
__device__ __forceinline__ void cp_wait1() {
    asm volatile("cp.async.wait_group 1;");
}
__device__ __forceinline__ float inv_freq_f(int i) {
    return expf(-(float)i * 0.28782313662425575f);
}
__device__ __forceinline__ void store_split(__nv_bfloat16* hi, __nv_bfloat16* lo,
                                            size_t idx, float v) {
    __nv_bfloat16 h = __float2bfloat16(v);
    hi[idx] = h;
    lo[idx] = __float2bfloat16(v - __bfloat162float(h));
}

// ---------------- qkv+rk tensor-core split-bf16 GEMM (3-stage cp.async)
//   fused rmsnorm + rope + scale epilogue -> Q/K/V splits
#define BM 128
#define BN 128
#define BK 32
#define AST 40
#define BST 136
#define NB1 (QKV_P / BN)     // 21 column-blocks for padded qkv+rk
#define NCH (D_MODEL / BK)   // 64 K-chunks
#define GA_OFF(buf, p) (((buf) * 2 + (p)) * BM * AST)
#define GB_OFF(buf, p) (6 * BM * AST + ((buf) * 2 + (p)) * BK * BST)
#define GSMEM_BYTES ((6 * BM * AST + 6 * BK * BST) * 2)

__device__ __forceinline__ void gemm_prefetch(
    unsigned sbase, int buf, int tid,
    const __nv_bfloat16* Ah, const __nv_bfloat16* Al,
    const __nv_bfloat16* Bh, const __nv_bfloat16* Bl,
    int m0, int n0, int kk0, int N, int K)
{
    const __nv_bfloat16* Ap[2];
    Ap[0] = Ah; Ap[1] = Al;
    const __nv_bfloat16* Bp[2];
    Bp[0] = Bh; Bp[1] = Bl;
    #pragma unroll
    for (int p = 0; p < 2; p++) {
        #pragma unroll
        for (int v = 0; v < 2; v++) {
            int vid = tid + v * 256;
            int ar = vid >> 2;
            int ac = (vid & 3) * 8;
            unsigned sa = sbase + (unsigned)(GA_OFF(buf, p) + ar * AST + ac) * 2u;
            cp16(sa, Ap[p] + (size_t)(m0 + ar) * K + kk0 + ac);
            int br = vid >> 4;
            int bc = (vid & 15) * 8;
            unsigned sb = sbase + (unsigned)(GB_OFF(buf, p) + br * BST + bc) * 2u;
            cp16(sb, Bp[p] + (size_t)(kk0 + br) * N + n0 + bc);
        }
    }
    cp_commit();
}

__global__ __launch_bounds__(256, 2)
void gemm_qkv(const __nv_bfloat16* __restrict__ Ah, const __nv_bfloat16* __restrict__ Al,
              const __nv_bfloat16* __restrict__ B1h, const __nv_bfloat16* __restrict__ B1l,
              const float* __restrict__ scaler, const float* __restrict__ brk, int K) {
    extern __shared__ __nv_bfloat16 gsm[];
    const unsigned sbase = (unsigned)__cvta_generic_to_shared(gsm);

    const int tid  = threadIdx.x;
    const int lane = tid & 31;
    const int wid  = tid >> 5;
    const int m0 = blockIdx.y * BM;
    const int wm = (wid & 3) * 32;
    const int wn = (wid >> 2) * 64;
    const int bx = blockIdx.x;
    const int N = QKV_P;
    const int n0 = bx * BN;

    float acc[2][8][4];
    #pragma unroll
    for (int mf = 0; mf < 2; mf++) {
        #pragma unroll
        for (int nf = 0; nf < 8; nf++) {
            #pragma unroll
            for (int i = 0; i < 4; i++) { acc[mf][nf][i] = 0.f; }
        }
    }

    const int l15 = lane & 15;
    const int l16 = (lane >> 4) << 3;

    gemm_prefetch(sbase, 0, tid, Ah, Al, B1h, B1l, m0, n0, 0, N, K);
    gemm_prefetch(sbase, 1, tid, Ah, Al, B1h, B1l, m0, n0, BK, N, K);

    for (int ch = 0; ch < NCH; ch++) {
        int buf = ch % 3;
        if (ch >= NCH - 2) { cp_wait0(); } else { cp_wait1(); }
        __syncthreads();
        if (ch + 2 < NCH) {
            gemm_prefetch(sbase, (ch + 2) % 3, tid, Ah, Al, B1h, B1l,
                          m0, n0, (ch + 2) * BK, N, K);
        }

        const unsigned a_b0 = sbase + (unsigned)GA_OFF(buf, 0) * 2u;
        const unsigned a_b1 = sbase + (unsigned)GA_OFF(buf, 1) * 2u;
        const unsigned b_b0 = sbase + (unsigned)GB_OFF(buf, 0) * 2u;
        const unsigned b_b1 = sbase + (unsigned)GB_OFF(buf, 1) * 2u;

        #pragma unroll
        for (int kk = 0; kk < BK; kk += 16) {
            uint32_t afh[2][4];
            uint32_t afl[2][4];
            uint32_t bfh[8][2];
            uint32_t bfl[8][2];
            #pragma unroll
            for (int mf = 0; mf < 2; mf++) {
                unsigned off = (unsigned)((wm + mf * 16 + l15) * AST + kk + l16) * 2u;
                ldsm_x4(afh[mf], a_b0 + off);
                ldsm_x4(afl[mf], a_b1 + off);
            }
            #pragma unroll
            for (int nb = 0; nb < 4; nb++) {
                unsigned off = (unsigned)((kk + l15) * BST + wn + nb * 16 + l16) * 2u;
                uint32_t th[4];
                uint32_t tl[4];
                ldsm_x4_t(th, b_b0 + off);
                ldsm_x4_t(tl, b_b1 + off);
                bfh[2 * nb][0] = th[0]; bfh[2 * nb][1] = th[1];
                bfh[2 * nb + 1][0] = th[2]; bfh[2 * nb + 1][1] = th[3];
                bfl[2 * nb][0] = tl[0]; bfl[2 * nb][1] = tl[1];
                bfl[2 * nb + 1][0] = tl[2]; bfl[2 * nb + 1][1] = tl[3];
            }
            #pragma unroll
            for (int mf = 0; mf < 2; mf++) {
                #pragma unroll
                for (int nf = 0; nf < 8; nf++) {
                    mma_bf16(acc[mf][nf], afh[mf], bfh[nf]);
                    mma_bf16(acc[mf][nf], afl[mf], bfh[nf]);
                    mma_bf16(acc[mf][nf], afh[mf], bfl[nf]);
                }
            }
        }
    }

    const int grp = lane >> 2;
    const int t2  = (lane & 3) * 2;

    // ---- fused rmsnorm / rope / scale epilogue ----
    float ssl[4];
    #pragma unroll
    for (int mf = 0; mf < 2; mf++) {
        float s0 = 0.f;
        float s1 = 0.f;
        #pragma unroll
        for (int nf = 0; nf < 8; nf++) {
            s0 += acc[mf][nf][0] * acc[mf][nf][0] + acc[mf][nf][1] * acc[mf][nf][1];
            s1 += acc[mf][nf][2] * acc[mf][nf][2] + acc[mf][nf][3] * acc[mf][nf][3];
        }
        ssl[mf * 2] = s0;
        ssl[mf * 2 + 1] = s1;
    }
    #pragma unroll
    for (int i = 0; i < 4; i++) {
        ssl[i] += __shfl_xor_sync(~0u, ssl[i], 1);
        ssl[i] += __shfl_xor_sync(~0u, ssl[i], 2);
    }
    float* red = (float*)gsm;
    __syncthreads();
    const int wnh = wid >> 2;
    if ((lane & 3) == 0) {
        #pragma unroll
        for (int mf = 0; mf < 2; mf++) {
            red[wnh * 128 + wm + mf * 16 + grp]     = ssl[mf * 2];
            red[wnh * 128 + wm + mf * 16 + grp + 8] = ssl[mf * 2 + 1];
        }
    }
    __syncthreads();

    #pragma unroll
    for (int mf = 0; mf < 2; mf++) {
        #pragma unroll
        for (int half = 0; half < 2; half++) {
            const int r = wm + mf * 16 + grp + half * 8;
            const int token = m0 + r;
            const int b = token >> 11;
            const int t = token & (T_SEQ - 1);
            const float ss = red[r] + red[128 + r];
            const float rn = rsqrtf(ss * (1.0f / 128.0f) + 1e-6f);

            if (bx < NH) {
                const int h = bx;
                const float sc = scaler[h] * logf(fminf((float)(t + 1), 1024.0f));
                const size_t qbase = ((size_t)((b * NH + h) * T_SEQ + t)) * DH;
                if (wn == 0) {
                    #pragma unroll
                    for (int nf = 0; nf < 8; nf++) {
                        #pragma unroll
                        for (int j = 0; j < 2; j++) {
                            int d = nf * 8 + t2 + j;
                            float val = acc[mf][nf][2 * half + j] * rn * sc;
                            store_split(g_Qh, g_Ql, qbase + d, val);
                        }
                    }
                } else {
                    #pragma unroll
                    for (int nf = 0; nf < 4; nf++) {
                        #pragma unroll
                        for (int j = 0; j < 2; j++) {
                            int i = nf * 8 + t2 + j;
                            float x1 = acc[mf][nf][2 * half + j] * rn;
                            float x2 = acc[mf][nf + 4][2 * half + j] * rn;
                            float f = (float)t * inv_freq_f(i);
                            float c = cosf(f);
                            float s = sinf(f);
                            store_split(g_Qh, g_Ql, qbase + 64 + i, sc * (x1 * c + x2 * s));
                            store_split(g_Qh, g_Ql, qbase + 96 + i, sc * (-x1 * s + x2 * c));
                        }
                    }
                }
            } else if (bx < NH + NKV) {
                const int kvh = bx - NH;
                const size_t kvbase = ((size_t)((b * NKV + kvh) * T_SEQ + t)) * DH;
                #pragma unroll
                for (int nf = 0; nf < 8; nf++) {
                    #pragma unroll
                    for (int j = 0; j < 2; j++) {
                        int d = wn + nf * 8 + t2 + j;
                        float val = acc[mf][nf][2 * half + j] * rn;
                        if (d < 64) {
                            store_split(g_Kh, g_Kl, kvbase + d, val);
                            store_split(g_Vh, g_Vl, kvbase + d, val);
                        } else {
                            store_split(g_Vh, g_Vl, kvbase + d, val);
                        }
                    }
                }
            } else {
                if (wn == 0) {
                    #pragma unroll
                    for (int nf = 0; nf < 4; nf++) {
                        #pragma unroll
                        for (int j = 0; j < 2; j++) {
                            int i = nf * 8 + t2 + j;
                            float x1 = acc[mf][nf][2 * half + j] + brk[i];
                            float x2 = acc[mf][nf + 4][2 * half + j] + brk[i + 32];
                            float f = (float)t * inv_freq_f(i);
                            float c = cosf(f);
                            float s = sinf(f);
                            float o1 = x1 * c + x2 * s;
                            float o2 = -x1 * s + x2 * c;
                            #pragma unroll
                            for (int kvh = 0; kvh < NKV; kvh++) {
                                size_t kvbase = ((size_t)((b * NKV + kvh) * T_SEQ + t)) * DH;
                                store_split(g_Kh, g_Kl, kvbase + 64 + i, o1);
                                store_split(g_Kh, g_Kl, kvbase + 96 + i, o2);
                            }
                        }
                    }
                }
            }
        }
    }
}

// ---------------- flash attention + fused g-tile GEMM + silu epilogue ----------------
#define ATQ 128
#define ATK 32
#define KST 136
#define AOF(buf, a) (((buf) * 4 + (a)) * ATK * KST)
// phase-2 smem layout (bytes): y stage at 0 (128*132*4 = 67584),
// gemm A at 69632 (4 * 10240), gemm B at 110592 (4 * 8704); total 145408
#define P2A(buf, p) (69632u + (unsigned)(((buf) * 2 + (p)) * BM * AST) * 2u)
#define P2B(buf, p) (110592u + (unsigned)(((buf) * 2 + (p)) * BK * BST) * 2u)
#define ASMEM_BYTES 145408

__device__ __forceinline__ void attn_prefetch(
    unsigned sbase, int buf, int tid, int k0,
    const __nv_bfloat16* Khp, const __nv_bfloat16* Klp,
    const __nv_bfloat16* Vhp, const __nv_bfloat16* Vlp)
{
    #pragma unroll
    for (int v = 0; v < 2; v++) {
        int idx = tid + v * 256;
        int r = idx >> 4;
        int c = (idx & 15) << 3;
        size_t goff = (size_t)(k0 + r) * DH + c;
        unsigned soff = (unsigned)(r * KST + c) * 2u;
        cp16(sbase + (unsigned)AOF(buf, 0) * 2u + soff, Khp + goff);
        cp16(sbase + (unsigned)AOF(buf, 1) * 2u + soff, Klp + goff);
        cp16(sbase + (unsigned)AOF(buf, 2) * 2u + soff, Vhp + goff);
        cp16(sbase + (unsigned)AOF(buf, 3) * 2u + soff, Vlp + goff);
    }
    cp_commit();
}

__device__ __forceinline__ void p2_prefetch(
    unsigned sbase, int buf, int tid,
    const __nv_bfloat16* Ah, const __nv_bfloat16* Al,
    const __nv_bfloat16* Bh, const __nv_bfloat16* Bl,
    int m0, int n0, int kk0)
{
    const __nv_bfloat16* Ap[2];
    Ap[0] = Ah; Ap[1] = Al;
    const __nv_bfloat16* Bp[2];
    Bp[0] = Bh; Bp[1] = Bl;
    #pragma unroll
    for (int p = 0; p < 2; p++) {
        #pragma unroll
        for (int v = 0; v < 2; v++) {
            int vid = tid + v * 256;
            int ar = vid >> 2;
            int ac = (vid & 3) * 8;
            cp16(sbase + P2A(buf, p) + (unsigned)(ar * AST + ac) * 2u,
                 Ap[p] + (size_t)(m0 + ar) * D_MODEL + kk0 + ac);
            int br = vid >> 4;
            int bc = (vid & 15) * 8;
            cp16(sbase + P2B(buf, p) + (unsigned)(br * BST + bc) * 2u,
                 Bp[p] + (size_t)(kk0 + br) * D_MODEL + n0 + bc);
        }
    }
    cp_commit();
}

__global__ __launch_bounds__(256) void attn_kernel(float* __restrict__ out) {
    extern __shared__ __nv_bfloat16 asmem[];
    const unsigned sbase = (unsigned)__cvta_generic_to_shared(asmem);

    // reversed mapping: heavy (large q0) blocks scheduled first
    const int q0  = (T_SEQ / ATQ - 1 - blockIdx.x) * ATQ;
    const int h   = blockIdx.y;
    const int b   = blockIdx.z;
    const int kvh = h >> 2;

    const int tid  = threadIdx.x;
    const int lane = tid & 31;
    const int wid  = tid >> 5;
    const int wm   = wid << 4;
    const int g    = lane >> 2;
    const int t2   = (lane & 3) << 1;
    const int l15  = lane & 15;
    const int l16o = (lane >> 4) << 3;

    const __nv_bfloat16* Qhp = g_Qh + ((size_t)((b * NH + h) * T_SEQ + q0 + wm)) * DH;
    const __nv_bfloat16* Qlp = g_Ql + ((size_t)((b * NH + h) * T_SEQ + q0 + wm)) * DH;
    uint32_t qh[8][4];
    uint32_t ql[8][4];
    #pragma unroll
    for (int kk = 0; kk < 8; kk++) {
        int c0 = kk * 16 + t2;
        qh[kk][0] = *(const uint32_t*)(Qhp + (size_t)g * DH + c0);
        qh[kk][1] = *(const uint32_t*)(Qhp + (size_t)(g + 8) * DH + c0);
        qh[kk][2] = *(const uint32_t*)(Qhp + (size_t)g * DH + c0 + 8);
        qh[kk][3] = *(const uint32_t*)(Qhp + (size_t)(g + 8) * DH + c0 + 8);
        ql[kk][0] = *(const uint32_t*)(Qlp + (size_t)g * DH + c0);
        ql[kk][1] = *(const uint32_t*)(Qlp + (size_t)(g + 8) * DH + c0);
        ql[kk][2] = *(const uint32_t*)(Qlp + (size_t)g * DH + c0 + 8);
        ql[kk][3] = *(const uint32_t*)(Qlp + (size_t)(g + 8) * DH + c0 + 8);
    }

    const __nv_bfloat16* Khp = g_Kh + ((size_t)((b * NKV + kvh) * T_SEQ)) * DH;
    const __nv_bfloat16* Klp = g_Kl + ((size_t)((b * NKV + kvh) * T_SEQ)) * DH;
    const __nv_bfloat16* Vhp = g_Vh + ((size_t)((b * NKV + kvh) * T_SEQ)) * DH;
    const __nv_bfloat16* Vlp = g_Vl + ((size_t)((b * NKV + kvh) * T_SEQ)) * DH;

    float o[16][4];
    #pragma unroll
    for (int nf = 0; nf < 16; nf++) {
        #pragma unroll
        for (int i = 0; i < 4; i++) { o[nf][i] = 0.f; }
    }
    float m0s = -1e30f;
    float m1s = -1e30f;
    float l0 = 0.f;
    float l1 = 0.f;

    const int gi0 = q0 + wm + g;
    const int gi1 = gi0 + 8;
    const int kstart = (q0 >= WSIZE) ? (q0 - WSIZE) : 0;
    const float sscale = 0.08838834764831845f;   // 1/sqrt(128)

    attn_prefetch(sbase, 0, tid, kstart, Khp, Klp, Vhp, Vlp);

    int buf = 0;
    for (int k0 = kstart; k0 < q0 + ATQ; k0 += ATK) {
        cp_wait0();
        __syncthreads();
        if (k0 + ATK < q0 + ATQ) {
            attn_prefetch(sbase, buf ^ 1, tid, k0 + ATK, Khp, Klp, Vhp, Vlp);
        }

        const unsigned skh_b = sbase + (unsigned)AOF(buf, 0) * 2u;
        const unsigned skl_b = sbase + (unsigned)AOF(buf, 1) * 2u;
        const unsigned svh_b = sbase + (unsigned)AOF(buf, 2) * 2u;
        const unsigned svl_b = sbase + (unsigned)AOF(buf, 3) * 2u;

        float s[4][4];
        #pragma unroll
        for (int nb = 0; nb < 4; nb++) {
            #pragma unroll
            for (int i = 0; i < 4; i++) { s[nb][i] = 0.f; }
        }
        #pragma unroll
        for (int kk = 0; kk < 8; kk++) {
            uint32_t kh0[4], kh1[4], kl0[4], kl1[4];
            unsigned off0 = (unsigned)((l15) * KST + kk * 16 + l16o) * 2u;
            unsigned off1 = (unsigned)((16 + l15) * KST + kk * 16 + l16o) * 2u;
            ldsm_x4(kh0, skh_b + off0);
            ldsm_x4(kh1, skh_b + off1);
            ldsm_x4(kl0, skl_b + off0);
            ldsm_x4(kl1, skl_b + off1);
            uint32_t bh[4][2];
            uint32_t bl[4][2];
            bh[0][0] = kh0[0]; bh[0][1] = kh0[2];
            bh[1][0] = kh0[1]; bh[1][1] = kh0[3];
            bh[2][0] = kh1[0]; bh[2][1] = kh1[2];
            bh[3][0] = kh1[1]; bh[3][1] = kh1[3];
            bl[0][0] = kl0[0]; bl[0][1] = kl0[2];
            bl[1][0] = kl0[1]; bl[1][1] = kl0[3];
            bl[2][0] = kl1[0]; bl[2][1] = kl1[2];
            bl[3][0] = kl1[1]; bl[3][1] = kl1[3];
            #pragma unroll
            for (int nb = 0; nb < 4; nb++) {
                mma_bf16(s[nb], qh[kk], bh[nb]);
                mma_bf16(s[nb], ql[kk], bh[nb]);
                mma_bf16(s[nb], qh[kk], bl[nb]);
            }
        }

        float mx0 = -1e30f;
        float mx1 = -1e30f;
        #pragma unroll
        for (int nb = 0; nb < 4; nb++) {
            #pragma unroll
            for (int ii = 0; ii < 2; ii++) {
                int j = k0 + nb * 8 + t2 + ii;
                float v0 = (j <= gi0 && j >= gi0 - WSIZE) ? s[nb][ii] * sscale : -1e30f;
                float v1 = (j <= gi1 && j >= gi1 - WSIZE) ? s[nb][2 + ii] * sscale : -1e30f;
                s[nb][ii] = v0;
                s[nb][2 + ii] = v1;
                mx0 = fmaxf(mx0, v0);
                mx1 = fmaxf(mx1, v1);
            }
        }
        mx0 = fmaxf(mx0, __shfl_xor_sync(~0u, mx0, 1));
        mx0 = fmaxf(mx0, __shfl_xor_sync(~0u, mx0, 2));
        mx1 = fmaxf(mx1, __shfl_xor_sync(~0u, mx1, 1));
        mx1 = fmaxf(mx1, __shfl_xor_sync(~0u, mx1, 2));
        float mn0 = fmaxf(m0s, mx0);
        float mn1 = fmaxf(m1s, mx1);
        float a0 = __expf(m0s - mn0);
        float a1 = __expf(m1s - mn1);
        m0s = mn0;
        m1s = mn1;

        float su0 = 0.f;
        float su1 = 0.f;
        uint32_t ph[2][4];
        uint32_t pl[2][4];
        #pragma unroll
        for (int nb = 0; nb < 4; nb++) {
            float p0 = __expf(s[nb][0] - mn0);
            float p1 = __expf(s[nb][1] - mn0);
            float p2 = __expf(s[nb][2] - mn1);
            float p3 = __expf(s[nb][3] - mn1);
            su0 += p0 + p1;
            su1 += p2 + p3;
            int c = nb >> 1;
            int half = (nb & 1) << 1;
            uint32_t h01 = pack_bf16x2(p0, p1);
            uint32_t h23 = pack_bf16x2(p2, p3);
            ph[c][half]     = h01;
            ph[c][half + 1] = h23;
            __nv_bfloat162* hp01 = (__nv_bfloat162*)&h01;
            __nv_bfloat162* hp23 = (__nv_bfloat162*)&h23;
            pl[c][half]     = pack_bf16x2(p0 - __bfloat162float(hp01->x),
                                          p1 - __bfloat162float(hp01->y));
            pl[c][half + 1] = pack_bf16x2(p2 - __bfloat162float(hp23->x),
                                          p3 - __bfloat162float(hp23->y));
        }
        su0 += __shfl_xor_sync(~0u, su0, 1);
        su0 += __shfl_xor_sync(~0u, su0, 2);
        su1 += __shfl_xor_sync(~0u, su1, 1);
        su1 += __shfl_xor_sync(~0u, su1, 2);
        l0 = l0 * a0 + su0;
        l1 = l1 * a1 + su1;

        #pragma unroll
        for (int nf = 0; nf < 16; nf++) {
            o[nf][0] *= a0;
            o[nf][1] *= a0;
            o[nf][2] *= a1;
            o[nf][3] *= a1;
        }

        #pragma unroll
        for (int c = 0; c < 2; c++) {
            #pragma unroll
            for (int nb = 0; nb < 8; nb++) {
                uint32_t vh4[4], vl4[4];
                unsigned off = (unsigned)((c * 16 + l15) * KST + nb * 16 + l16o) * 2u;
                ldsm_x4_t(vh4, svh_b + off);
                ldsm_x4_t(vl4, svl_b + off);
                uint32_t b0h[2], b1h[2], b0l[2], b1l[2];
                b0h[0] = vh4[0]; b0h[1] = vh4[1];
                b1h[0] = vh4[2]; b1h[1] = vh4[3];
                b0l[0] = vl4[0]; b0l[1] = vl4[1];
                b1l[0] = vl4[2]; b1l[1] = vl4[3];
                mma_bf16(o[2 * nb],     ph[c], b0h);
                mma_bf16(o[2 * nb],     pl[c], b0h);
                mma_bf16(o[2 * nb],     ph[c], b0l);
                mma_bf16(o[2 * nb + 1], ph[c], b1h);
                mma_bf16(o[2 * nb + 1], pl[c], b1h);
                mma_bf16(o[2 * nb + 1], ph[c], b1l);
            }
        }
        buf ^= 1;
    }

    // ================= phase 2: fused g-tile GEMM + silu =================
    const int gm0 = b * T_SEQ + q0;      // A row base (token)
    const int gn0 = h * DH;              // B col base

    // first prefetch uses regions disjoint from the K/V tiles -> no sync needed yet
    p2_prefetch(sbase, 0, tid, g_Ah, g_Al, g_Bgh, g_Bgl, gm0, gn0, 0);

    // stage y = o / l into smem (overwrites old K/V region; sync first)
    __syncthreads();
    float* ysm = (float*)asmem;          // [128][132]
    {
        const float il0 = 1.0f / l0;
        const float il1 = 1.0f / l1;
        #pragma unroll
        for (int nf = 0; nf < 16; nf++) {
            int d = nf * 8 + t2;
            *(float2*)&ysm[(wm + g) * 132 + d] =
                make_float2(o[nf][0] * il0, o[nf][1] * il0);
            *(float2*)&ysm[(wm + g + 8) * 132 + d] =
                make_float2(o[nf][2] * il1, o[nf][3] * il1);
        }
    }

    // gemm accumulators (reuse registers freed from o/q frags)
    float acc[2][8][4];
    #pragma unroll
    for (int mf = 0; mf < 2; mf++) {
        #pragma unroll
        for (int nf = 0; nf < 8; nf++) {
            #pragma unroll
            for (int i = 0; i < 4; i++) { acc[mf][nf][i] = 0.f; }
        }
    }

    const int wmg = (wid & 3) * 32;
    const int wng = (wid >> 2) * 64;

    int gbuf = 0;
    for (int ch = 0; ch < NCH; ch++) {
        cp_wait0();
        __syncthreads();
        if (ch + 1 < NCH) {
            p2_prefetch(sbase, gbuf ^ 1, tid, g_Ah, g_Al, g_Bgh, g_Bgl,
                        gm0, gn0, (ch + 1) * BK);
        }

        const unsigned a_b0 = sbase + P2A(gbuf, 0);
        const unsigned a_b1 = sbase + P2A(gbuf, 1);
        const unsigned b_b0 = sbase + P2B(gbuf, 0);
        const unsigned b_b1 = sbase + P2B(gbuf, 1);

        #pragma unroll
        for (int kk = 0; kk < BK; kk += 16) {
            uint32_t afh[2][4];
            uint32_t afl[2][4];
            uint32_t bfh[8][2];
            uint32_t bfl[8][2];
            #pragma unroll
            for (int mf = 0; mf < 2; mf++) {
                unsigned off = (unsigned)((wmg + mf * 16 + l15) * AST + kk + l16o) * 2u;
                ldsm_x4(afh[mf], a_b0 + off);
                ldsm_x4(afl[mf], a_b1 + off);
            }
            #pragma unroll
            for (int nb = 0; nb < 4; nb++) {
                unsigned off = (unsigned)((kk + l15) * BST + wng + nb * 16 + l16o) * 2u;
                uint32_t th[4];
                uint32_t tl[4];
                ldsm_x4_t(th, b_b0 + off);
                ldsm_x4_t(tl, b_b1 + off);
                bfh[2 * nb][0] = th[0]; bfh[2 * nb][1] = th[1];
                bfh[2 * nb + 1][0] = th[2]; bfh[2 * nb + 1][1] = th[3];
                bfl[2 * nb][0] = tl[0]; bfl[2 * nb][1] = tl[1];
                bfl[2 * nb + 1][0] = tl[2]; bfl[2 * nb + 1][1] = tl[3];
            }
            #pragma unroll
            for (int mf = 0; mf < 2; mf++) {
                #pragma unroll
                for (int nf = 0; nf < 8; nf++) {
                    mma_bf16(acc[mf][nf], afh[mf], bfh[nf]);
                    mma_bf16(acc[mf][nf], afl[mf], bfh[nf]);
                    mma_bf16(acc[mf][nf], afh[mf], bfl[nf]);
                }
            }
        }
        gbuf ^= 1;
    }

    // ---- silu epilogue: out = y * silu(g) ----
    const int grp = lane >> 2;
    #pragma unroll
    for (int mf = 0; mf < 2; mf++) {
        #pragma unroll
        for (int half = 0; half < 2; half++) {
            const int r = wmg + mf * 16 + grp + half * 8;
            float* orow = out + ((size_t)(gm0 + r)) * D_MODEL + gn0;
            #pragma unroll
            for (int nf = 0; nf < 8; nf++) {
                int col = wng + nf * 8 + t2;
                float g0 = acc[mf][nf][2 * half];
                float g1 = acc[mf][nf][2 * half + 1];
                float y0 = ysm[r * 132 + col];
                float y1 = ysm[r * 132 + col + 1];
                float2 rv;
                rv.x = y0 * g0 / (1.0f + expf(-g0));
                rv.y = y1 * g1 / (1.0f + expf(-g1));
                *(float2*)(orow + col) = rv;
            }
        }
    }
}

// ---------------- launch ----------------
extern "C" void kernel_launch(void* const* d_in, const int* in_sizes, int n_in,
                              void* d_out, int out_size) {
    const float* x      = (const float*)d_in[0];
    const float* Wqkv   = (const float*)d_in[1];
    const float* Wrk    = (const float*)d_in[2];
    const float* brk    = (const float*)d_in[3];
    const float* scaler = (const float*)d_in[4];
    const float* Wg     = (const float*)d_in[5];
    float* out = (float*)d_out;

    __nv_bfloat16* p_Ah;
    __nv_bfloat16* p_Al;
    __nv_bfloat16* p_Bqh;
    __nv_bfloat16* p_Bql;
    __nv_bfloat16* p_Bgh;
    __nv_bfloat16* p_Bgl;
    cudaGetSymbolAddress((void**)&p_Ah,  g_Ah);
    cudaGetSymbolAddress((void**)&p_Al,  g_Al);
    cudaGetSymbolAddress((void**)&p_Bqh, g_Bqh);
    cudaGetSymbolAddress((void**)&p_Bql, g_Bql);
    cudaGetSymbolAddress((void**)&p_Bgh, g_Bgh);
    cudaGetSymbolAddress((void**)&p_Bgl, g_Bgl);

    cudaFuncSetAttribute(gemm_qkv,
                         cudaFuncAttributeMaxDynamicSharedMemorySize, GSMEM_BYTES);
    cudaFuncSetAttribute(attn_kernel,
                         cudaFuncAttributeMaxDynamicSharedMemorySize, ASMEM_BYTES);

    cvt_split<<<(BT * D_MODEL + 255) / 256, 256>>>(x, p_Ah, p_Al, BT * D_MODEL);
    cvt_split_pad<<<(D_MODEL * QKV_N + 255) / 256, 256>>>(
        Wqkv, p_Bqh, p_Bql, D_MODEL, QKV_N, QKV_P, 0);
    cvt_split_pad<<<(D_MODEL * D2 + 255) / 256, 256>>>(
        Wrk, p_Bqh, p_Bql, D_MODEL, D2, QKV_P, QKV_N);
    cvt_split<<<(D_MODEL * D_MODEL + 255) / 256, 256>>>(Wg, p_Bgh, p_Bgl, D_MODEL * D_MODEL);

    gemm_qkv<<<dim3(NB1, BT / BM), 256, GSMEM_BYTES>>>(
        p_Ah, p_Al, p_Bqh, p_Bql, scaler, brk, D_MODEL);

    attn_kernel<<<dim3(T_SEQ / ATQ, NH, B_SZ), 256, ASMEM_BYTES>>>(out);
}

// round 17
// speedup vs baseline: 1.1152x; 1.1152x over previous
#include <cuda_runtime.h>
#include <cuda_bf16.h>
#include <stdint.h>
#include <math.h>

#define D_MODEL 2048
#define NH      16
#define NKV     4
#define DH      128
#define D1      64
#define D2      64
#define T_SEQ   2048
#define B_SZ    2
#define BT      (B_SZ * T_SEQ)          // 4096
#define WSIZE   1024
#define QKV_N   ((NH + NKV) * DH)       // 2560
#define QKV_P   2688                    // padded: qkv (2560) + rk (64) + zero pad (64)

// ---------------- scratch (device globals; no runtime allocation) ----------------
__device__ float g_gmat[BT * D_MODEL];               // raw x@W_g

// split-bf16 Q/K/V
__device__ __nv_bfloat16 g_Qh[B_SZ * NH  * T_SEQ * DH];
__device__ __nv_bfloat16 g_Ql[B_SZ * NH  * T_SEQ * DH];
__device__ __nv_bfloat16 g_Kh[B_SZ * NKV * T_SEQ * DH];
__device__ __nv_bfloat16 g_Kl[B_SZ * NKV * T_SEQ * DH];
__device__ __nv_bfloat16 g_Vh[B_SZ * NKV * T_SEQ * DH];
__device__ __nv_bfloat16 g_Vl[B_SZ * NKV * T_SEQ * DH];

// split-bf16 GEMM operand copies
__device__ __nv_bfloat16 g_Ah [BT * D_MODEL];
__device__ __nv_bfloat16 g_Al [BT * D_MODEL];
__device__ __nv_bfloat16 g_Bqh[D_MODEL * QKV_P];     // pad cols stay zero (BSS init)
__device__ __nv_bfloat16 g_Bql[D_MODEL * QKV_P];
__device__ __nv_bfloat16 g_Bgh[D_MODEL * D_MODEL];
__device__ __nv_bfloat16 g_Bgl[D_MODEL * D_MODEL];

// ---------------- merged fp32 -> (hi, lo) bf16 split for all operands ----------------
#define CVT_N0 (BT * D_MODEL)                 // x
#define CVT_N1 (CVT_N0 + D_MODEL * QKV_N)     // + Wqkv
#define CVT_N2 (CVT_N1 + D_MODEL * D2)        // + Wrk
#define CVT_N3 (CVT_N2 + D_MODEL * D_MODEL)   // + Wg

__global__ void cvt_all(const float* __restrict__ x, const float* __restrict__ Wqkv,
                        const float* __restrict__ Wrk, const float* __restrict__ Wg) {
    int i = blockIdx.x * 256 + threadIdx.x;
    float f;
    __nv_bfloat16* hi;
    __nv_bfloat16* lo;
    size_t o;
    if (i < CVT_N0) {
        f = x[i];
        hi = g_Ah; lo = g_Al; o = (size_t)i;
    } else if (i < CVT_N1) {
        int j = i - CVT_N0;
        int r = j / QKV_N;
        int c = j - r * QKV_N;
        f = Wqkv[j];
        hi = g_Bqh; lo = g_Bql; o = (size_t)r * QKV_P + c;
    } else if (i < CVT_N2) {
        int j = i - CVT_N1;
        int r = j >> 6;
        int c = j & 63;
        f = Wrk[j];
        hi = g_Bqh; lo = g_Bql; o = (size_t)r * QKV_P + QKV_N + c;
    } else if (i < CVT_N3) {
        int j = i - CVT_N2;
        f = Wg[j];
        hi = g_Bgh; lo = g_Bgl; o = (size_t)j;
    } else {
        return;
    }
    __nv_bfloat16 h = __float2bfloat16(f);
    hi[o] = h;
    lo[o] = __float2bfloat16(f - __bfloat162float(h));
}

// ---------------- mma / ldmatrix / cp.async helpers ----------------
__device__ __forceinline__ void ldsm_x4(uint32_t* r, unsigned addr) {
    asm volatile("ldmatrix.sync.aligned.m8n8.x4.shared.b16 {%0,%1,%2,%3}, [%4];"
        : "=r"(r[0]), "=r"(r[1]), "=r"(r[2]), "=r"(r[3]) : "r"(addr));
}
__device__ __forceinline__ void ldsm_x4_t(uint32_t* r, unsigned addr) {
    asm volatile("ldmatrix.sync.aligned.m8n8.x4.trans.shared.b16 {%0,%1,%2,%3}, [%4];"
        : "=r"(r[0]), "=r"(r[1]), "=r"(r[2]), "=r"(r[3]) : "r"(addr));
}
__device__ __forceinline__ void mma_bf16(float* d, const uint32_t* a, const uint32_t* b) {
    asm volatile("mma.sync.aligned.m16n8k16.row.col.f32.bf16.bf16.f32 "
        "{%0,%1,%2,%3}, {%4,%5,%6,%7}, {%8,%9}, {%0,%1,%2,%3};"
        : "+f"(d[0]), "+f"(d[1]), "+f"(d[2]), "+f"(d[3])
        : "r"(a[0]), "r"(a[1]), "r"(a[2]), "r"(a[3]), "r"(b[0]), "r"(b[1]));
}
__device__ __forceinline__ uint32_t pack_bf16x2(float x, float y) {
    __nv_bfloat162 t = __floats2bfloat162_rn(x, y);
    return *(uint32_t*)&t;
}
__device__ __forceinline__ void cp16(unsigned saddr, const void* gptr) {
    asm volatile("cp.async.cg.shared.global [%0], [%1], 16;" :: "r"(saddr), "l"(gptr));
}
__device__ __forceinline__ void cp_commit() {
    asm volatile("cp.async.commit_group;");
}
__device__ __forceinline__ void cp_wait0() {
    asm volatile("cp.async.wait_group 0;");
}
__device__ __forceinline__ void cp_wait1() {
    asm volatile("cp.async.wait_group 1;");
}
__device__ __forceinline__ float inv_freq_f(int i) {
    return expf(-(float)i * 0.28782313662425575f);
}
__device__ __forceinline__ void store_split(__nv_bfloat16* hi, __nv_bfloat16* lo,
                                            size_t idx, float v) {
    __nv_bfloat16 h = __float2bfloat16(v);
    hi[idx] = h;
    lo[idx] = __float2bfloat16(v - __bfloat162float(h));
}

// ---------------- merged tensor-core split-bf16 GEMM (3-stage cp.async)
//   C1 blocks (bx < NB1): fused rmsnorm + rope + scale epilogue -> Q/K/V splits
//   C2 blocks: plain fp32 store to g_gmat
#define BM 128
#define BN 128
#define BK 32
#define AST 40
#define BST 136
#define NB1 (QKV_P / BN)     // 21 column-blocks for padded qkv+rk
#define NB2 (D_MODEL / BN)   // 16 column-blocks for g
#define NCH (D_MODEL / BK)   // 64 K-chunks
#define GA_OFF(buf, p) (((buf) * 2 + (p)) * BM * AST)
#define GB_OFF(buf, p) (6 * BM * AST + ((buf) * 2 + (p)) * BK * BST)
#define GSMEM_BYTES ((6 * BM * AST + 6 * BK * BST) * 2)

__device__ __forceinline__ void gemm_prefetch(
    unsigned sbase, int buf, int tid,
    const __nv_bfloat16* Ah, const __nv_bfloat16* Al,
    const __nv_bfloat16* Bh, const __nv_bfloat16* Bl,
    int m0, int n0, int kk0, int N, int K)
{
    const __nv_bfloat16* Ap[2];
    Ap[0] = Ah; Ap[1] = Al;
    const __nv_bfloat16* Bp[2];
    Bp[0] = Bh; Bp[1] = Bl;
    #pragma unroll
    for (int p = 0; p < 2; p++) {
        #pragma unroll
        for (int v = 0; v < 2; v++) {
            int vid = tid + v * 256;
            int ar = vid >> 2;
            int ac = (vid & 3) * 8;
            unsigned sa = sbase + (unsigned)(GA_OFF(buf, p) + ar * AST + ac) * 2u;
            cp16(sa, Ap[p] + (size_t)(m0 + ar) * K + kk0 + ac);
            int br = vid >> 4;
            int bc = (vid & 15) * 8;
            unsigned sb = sbase + (unsigned)(GB_OFF(buf, p) + br * BST + bc) * 2u;
            cp16(sb, Bp[p] + (size_t)(kk0 + br) * N + n0 + bc);
        }
    }
    cp_commit();
}

__global__ __launch_bounds__(256, 2)
void gemm_bf16x3_dual(const __nv_bfloat16* __restrict__ Ah, const __nv_bfloat16* __restrict__ Al,
                      const __nv_bfloat16* __restrict__ B1h, const __nv_bfloat16* __restrict__ B1l,
                      const __nv_bfloat16* __restrict__ B2h, const __nv_bfloat16* __restrict__ B2l,
                      float* __restrict__ C2,
                      const float* __restrict__ scaler, const float* __restrict__ brk,
                      int K) {
    extern __shared__ __nv_bfloat16 gsm[];
    const unsigned sbase = (unsigned)__cvta_generic_to_shared(gsm);

    const int tid  = threadIdx.x;
    const int lane = tid & 31;
    const int wid  = tid >> 5;
    const int m0 = blockIdx.y * BM;
    const int wm = (wid & 3) * 32;
    const int wn = (wid >> 2) * 64;
    const int bx = blockIdx.x;

    const __nv_bfloat16* Bh;
    const __nv_bfloat16* Bl;
    int N;
    int n0;
    if (bx < NB1) {
        Bh = B1h; Bl = B1l; N = QKV_P; n0 = bx * BN;
    } else {
        Bh = B2h; Bl = B2l; N = D_MODEL; n0 = (bx - NB1) * BN;
    }

    float acc[2][8][4];
    #pragma unroll
    for (int mf = 0; mf < 2; mf++) {
        #pragma unroll
        for (int nf = 0; nf < 8; nf++) {
            #pragma unroll
            for (int i = 0; i < 4; i++) { acc[mf][nf][i] = 0.f; }
        }
    }

    const int l15 = lane & 15;
    const int l16 = (lane >> 4) << 3;

    gemm_prefetch(sbase, 0, tid, Ah, Al, Bh, Bl, m0, n0, 0, N, K);
    gemm_prefetch(sbase, 1, tid, Ah, Al, Bh, Bl, m0, n0, BK, N, K);

    for (int ch = 0; ch < NCH; ch++) {
        int buf = ch % 3;
        if (ch >= NCH - 2) { cp_wait0(); } else { cp_wait1(); }
        __syncthreads();
        if (ch + 2 < NCH) {
            gemm_prefetch(sbase, (ch + 2) % 3, tid, Ah, Al, Bh, Bl,
                          m0, n0, (ch + 2) * BK, N, K);
        }

        const unsigned a_b0 = sbase + (unsigned)GA_OFF(buf, 0) * 2u;
        const unsigned a_b1 = sbase + (unsigned)GA_OFF(buf, 1) * 2u;
        const unsigned b_b0 = sbase + (unsigned)GB_OFF(buf, 0) * 2u;
        const unsigned b_b1 = sbase + (unsigned)GB_OFF(buf, 1) * 2u;

        #pragma unroll
        for (int kk = 0; kk < BK; kk += 16) {
            uint32_t afh[2][4];
            uint32_t afl[2][4];
            uint32_t bfh[8][2];
            uint32_t bfl[8][2];
            #pragma unroll
            for (int mf = 0; mf < 2; mf++) {
                unsigned off = (unsigned)((wm + mf * 16 + l15) * AST + kk + l16) * 2u;
                ldsm_x4(afh[mf], a_b0 + off);
                ldsm_x4(afl[mf], a_b1 + off);
            }
            #pragma unroll
            for (int nb = 0; nb < 4; nb++) {
                unsigned off = (unsigned)((kk + l15) * BST + wn + nb * 16 + l16) * 2u;
                uint32_t th[4];
                uint32_t tl[4];
                ldsm_x4_t(th, b_b0 + off);
                ldsm_x4_t(tl, b_b1 + off);
                bfh[2 * nb][0] = th[0]; bfh[2 * nb][1] = th[1];
                bfh[2 * nb + 1][0] = th[2]; bfh[2 * nb + 1][1] = th[3];
                bfl[2 * nb][0] = tl[0]; bfl[2 * nb][1] = tl[1];
                bfl[2 * nb + 1][0] = tl[2]; bfl[2 * nb + 1][1] = tl[3];
            }
            // pass 1: hi*hi (16 independent mma), pass 2: lo*hi, pass 3: hi*lo
            #pragma unroll
            for (int mf = 0; mf < 2; mf++) {
                #pragma unroll
                for (int nf = 0; nf < 8; nf++) { mma_bf16(acc[mf][nf], afh[mf], bfh[nf]); }
            }
            #pragma unroll
            for (int mf = 0; mf < 2; mf++) {
                #pragma unroll
                for (int nf = 0; nf < 8; nf++) { mma_bf16(acc[mf][nf], afl[mf], bfh[nf]); }
            }
            #pragma unroll
            for (int mf = 0; mf < 2; mf++) {
                #pragma unroll
                for (int nf = 0; nf < 8; nf++) { mma_bf16(acc[mf][nf], afh[mf], bfl[nf]); }
            }
        }
    }

    const int grp = lane >> 2;
    const int t2  = (lane & 3) * 2;

    if (bx >= NB1) {
        #pragma unroll
        for (int mf = 0; mf < 2; mf++) {
            #pragma unroll
            for (int nf = 0; nf < 8; nf++) {
                float* c0 = C2 + (size_t)(m0 + wm + mf * 16 + grp) * N + n0 + wn + nf * 8 + t2;
                *(float2*)c0 = make_float2(acc[mf][nf][0], acc[mf][nf][1]);
                float* c1 = c0 + (size_t)8 * N;
                *(float2*)c1 = make_float2(acc[mf][nf][2], acc[mf][nf][3]);
            }
        }
        return;
    }

    // ---- fused rmsnorm / rope / scale epilogue ----
    float ssl[4];
    #pragma unroll
    for (int mf = 0; mf < 2; mf++) {
        float s0 = 0.f;
        float s1 = 0.f;
        #pragma unroll
        for (int nf = 0; nf < 8; nf++) {
            s0 += acc[mf][nf][0] * acc[mf][nf][0] + acc[mf][nf][1] * acc[mf][nf][1];
            s1 += acc[mf][nf][2] * acc[mf][nf][2] + acc[mf][nf][3] * acc[mf][nf][3];
        }
        ssl[mf * 2] = s0;
        ssl[mf * 2 + 1] = s1;
    }
    #pragma unroll
    for (int i = 0; i < 4; i++) {
        ssl[i] += __shfl_xor_sync(~0u, ssl[i], 1);
        ssl[i] += __shfl_xor_sync(~0u, ssl[i], 2);
    }
    float* red = (float*)gsm;
    __syncthreads();
    const int wnh = wid >> 2;
    if ((lane & 3) == 0) {
        #pragma unroll
        for (int mf = 0; mf < 2; mf++) {
            red[wnh * 128 + wm + mf * 16 + grp]     = ssl[mf * 2];
            red[wnh * 128 + wm + mf * 16 + grp + 8] = ssl[mf * 2 + 1];
        }
    }
    __syncthreads();

    #pragma unroll
    for (int mf = 0; mf < 2; mf++) {
        #pragma unroll
        for (int half = 0; half < 2; half++) {
            const int r = wm + mf * 16 + grp + half * 8;
            const int token = m0 + r;
            const int b = token >> 11;
            const int t = token & (T_SEQ - 1);
            const float ss = red[r] + red[128 + r];
            const float rn = rsqrtf(ss * (1.0f / 128.0f) + 1e-6f);

            if (bx < NH) {
                const int h = bx;
                const float sc = scaler[h] * logf(fminf((float)(t + 1), 1024.0f));
                const size_t qbase = ((size_t)((b * NH + h) * T_SEQ + t)) * DH;
                if (wn == 0) {
                    #pragma unroll
                    for (int nf = 0; nf < 8; nf++) {
                        #pragma unroll
                        for (int j = 0; j < 2; j++) {
                            int d = nf * 8 + t2 + j;
                            float val = acc[mf][nf][2 * half + j] * rn * sc;
                            store_split(g_Qh, g_Ql, qbase + d, val);
                        }
                    }
                } else {
                    #pragma unroll
                    for (int nf = 0; nf < 4; nf++) {
                        #pragma unroll
                        for (int j = 0; j < 2; j++) {
                            int i = nf * 8 + t2 + j;
                            float x1 = acc[mf][nf][2 * half + j] * rn;
                            float x2 = acc[mf][nf + 4][2 * half + j] * rn;
                            float f = (float)t * inv_freq_f(i);
                            float c = cosf(f);
                            float s = sinf(f);
                            store_split(g_Qh, g_Ql, qbase + 64 + i, sc * (x1 * c + x2 * s));
                            store_split(g_Qh, g_Ql, qbase + 96 + i, sc * (-x1 * s + x2 * c));
                        }
                    }
                }
            } else if (bx < NH + NKV) {
                const int kvh = bx - NH;
                const size_t kvbase = ((size_t)((b * NKV + kvh) * T_SEQ + t)) * DH;
                #pragma unroll
                for (int nf = 0; nf < 8; nf++) {
                    #pragma unroll
                    for (int j = 0; j < 2; j++) {
                        int d = wn + nf * 8 + t2 + j;
                        float val = acc[mf][nf][2 * half + j] * rn;
                        if (d < 64) {
                            store_split(g_Kh, g_Kl, kvbase + d, val);
                            store_split(g_Vh, g_Vl, kvbase + d, val);
                        } else {
                            store_split(g_Vh, g_Vl, kvbase + d, val);
                        }
                    }
                }
            } else {
                if (wn == 0) {
                    #pragma unroll
                    for (int nf = 0; nf < 4; nf++) {
                        #pragma unroll
                        for (int j = 0; j < 2; j++) {
                            int i = nf * 8 + t2 + j;
                            float x1 = acc[mf][nf][2 * half + j] + brk[i];
                            float x2 = acc[mf][nf + 4][2 * half + j] + brk[i + 32];
                            float f = (float)t * inv_freq_f(i);
                            float c = cosf(f);
                            float s = sinf(f);
                            float o1 = x1 * c + x2 * s;
                            float o2 = -x1 * s + x2 * c;
                            #pragma unroll
                            for (int kvh = 0; kvh < NKV; kvh++) {
                                size_t kvbase = ((size_t)((b * NKV + kvh) * T_SEQ + t)) * DH;
                                store_split(g_Kh, g_Kl, kvbase + 64 + i, o1);
                                store_split(g_Kh, g_Kl, kvbase + 96 + i, o2);
                            }
                        }
                    }
                }
            }
        }
    }
}

// ---------------- tensor-core windowed flash attention + fused silu epilogue ----------------
#define ATQ 128
#define ATK 32
#define KST 136
#define AOF(buf, a) (((buf) * 4 + (a)) * ATK * KST)
#define ASMEM_BYTES (8 * ATK * KST * 2)

__device__ __forceinline__ void attn_prefetch(
    unsigned sbase, int buf, int tid, int k0,
    const __nv_bfloat16* Khp, const __nv_bfloat16* Klp,
    const __nv_bfloat16* Vhp, const __nv_bfloat16* Vlp)
{
    #pragma unroll
    for (int v = 0; v < 2; v++) {
        int idx = tid + v * 256;
        int r = idx >> 4;
        int c = (idx & 15) << 3;
        size_t goff = (size_t)(k0 + r) * DH + c;
        unsigned soff = (unsigned)(r * KST + c) * 2u;
        cp16(sbase + (unsigned)AOF(buf, 0) * 2u + soff, Khp + goff);
        cp16(sbase + (unsigned)AOF(buf, 1) * 2u + soff, Klp + goff);
        cp16(sbase + (unsigned)AOF(buf, 2) * 2u + soff, Vhp + goff);
        cp16(sbase + (unsigned)AOF(buf, 3) * 2u + soff, Vlp + goff);
    }
    cp_commit();
}

__global__ __launch_bounds__(256) void attn_kernel(float* __restrict__ out) {
    extern __shared__ __nv_bfloat16 asmem[];
    const unsigned sbase = (unsigned)__cvta_generic_to_shared(asmem);

    // reversed mapping: heavy (large q0) blocks scheduled first
    const int q0  = (T_SEQ / ATQ - 1 - blockIdx.x) * ATQ;
    const int h   = blockIdx.y;
    const int b   = blockIdx.z;
    const int kvh = h >> 2;

    const int tid  = threadIdx.x;
    const int lane = tid & 31;
    const int wid  = tid >> 5;
    const int wm   = wid << 4;
    const int g    = lane >> 2;
    const int t2   = (lane & 3) << 1;
    const int l15  = lane & 15;
    const int l16o = (lane >> 4) << 3;

    const __nv_bfloat16* Qhp = g_Qh + ((size_t)((b * NH + h) * T_SEQ + q0 + wm)) * DH;
    const __nv_bfloat16* Qlp = g_Ql + ((size_t)((b * NH + h) * T_SEQ + q0 + wm)) * DH;
    uint32_t qh[8][4];
    uint32_t ql[8][4];
    #pragma unroll
    for (int kk = 0; kk < 8; kk++) {
        int c0 = kk * 16 + t2;
        qh[kk][0] = *(const uint32_t*)(Qhp + (size_t)g * DH + c0);
        qh[kk][1] = *(const uint32_t*)(Qhp + (size_t)(g + 8) * DH + c0);
        qh[kk][2] = *(const uint32_t*)(Qhp + (size_t)g * DH + c0 + 8);
        qh[kk][3] = *(const uint32_t*)(Qhp + (size_t)(g + 8) * DH + c0 + 8);
        ql[kk][0] = *(const uint32_t*)(Qlp + (size_t)g * DH + c0);
        ql[kk][1] = *(const uint32_t*)(Qlp + (size_t)(g + 8) * DH + c0);
        ql[kk][2] = *(const uint32_t*)(Qlp + (size_t)g * DH + c0 + 8);
        ql[kk][3] = *(const uint32_t*)(Qlp + (size_t)(g + 8) * DH + c0 + 8);
    }

    const __nv_bfloat16* Khp = g_Kh + ((size_t)((b * NKV + kvh) * T_SEQ)) * DH;
    const __nv_bfloat16* Klp = g_Kl + ((size_t)((b * NKV + kvh) * T_SEQ)) * DH;
    const __nv_bfloat16* Vhp = g_Vh + ((size_t)((b * NKV + kvh) * T_SEQ)) * DH;
    const __nv_bfloat16* Vlp = g_Vl + ((size_t)((b * NKV + kvh) * T_SEQ)) * DH;

    float o[16][4];
    #pragma unroll
    for (int nf = 0; nf < 16; nf++) {
        #pragma unroll
        for (int i = 0; i < 4; i++) { o[nf][i] = 0.f; }
    }
    float m0s = -1e30f;
    float m1s = -1e30f;
    float l0 = 0.f;
    float l1 = 0.f;

    const int gi0 = q0 + wm + g;
    const int gi1 = gi0 + 8;
    const int kstart = (q0 >= WSIZE) ? (q0 - WSIZE) : 0;
    const float sscale = 0.08838834764831845f;   // 1/sqrt(128)

    attn_prefetch(sbase, 0, tid, kstart, Khp, Klp, Vhp, Vlp);

    int buf = 0;
    for (int k0 = kstart; k0 < q0 + ATQ; k0 += ATK) {
        cp_wait0();
        __syncthreads();
        if (k0 + ATK < q0 + ATQ) {
            attn_prefetch(sbase, buf ^ 1, tid, k0 + ATK, Khp, Klp, Vhp, Vlp);
        }

        const unsigned skh_b = sbase + (unsigned)AOF(buf, 0) * 2u;
        const unsigned skl_b = sbase + (unsigned)AOF(buf, 1) * 2u;
        const unsigned svh_b = sbase + (unsigned)AOF(buf, 2) * 2u;
        const unsigned svl_b = sbase + (unsigned)AOF(buf, 3) * 2u;

        float s[4][4];
        #pragma unroll
        for (int nb = 0; nb < 4; nb++) {
            #pragma unroll
            for (int i = 0; i < 4; i++) { s[nb][i] = 0.f; }
        }
        #pragma unroll
        for (int kk = 0; kk < 8; kk++) {
            uint32_t kh0[4], kh1[4], kl0[4], kl1[4];
            unsigned off0 = (unsigned)((l15) * KST + kk * 16 + l16o) * 2u;
            unsigned off1 = (unsigned)((16 + l15) * KST + kk * 16 + l16o) * 2u;
            ldsm_x4(kh0, skh_b + off0);
            ldsm_x4(kh1, skh_b + off1);
            ldsm_x4(kl0, skl_b + off0);
            ldsm_x4(kl1, skl_b + off1);
            uint32_t bh[4][2];
            uint32_t bl[4][2];
            bh[0][0] = kh0[0]; bh[0][1] = kh0[2];
            bh[1][0] = kh0[1]; bh[1][1] = kh0[3];
            bh[2][0] = kh1[0]; bh[2][1] = kh1[2];
            bh[3][0] = kh1[1]; bh[3][1] = kh1[3];
            bl[0][0] = kl0[0]; bl[0][1] = kl0[2];
            bl[1][0] = kl0[1]; bl[1][1] = kl0[3];
            bl[2][0] = kl1[0]; bl[2][1] = kl1[2];
            bl[3][0] = kl1[1]; bl[3][1] = kl1[3];
            // independent-accumulator passes
            #pragma unroll
            for (int nb = 0; nb < 4; nb++) { mma_bf16(s[nb], qh[kk], bh[nb]); }
            #pragma unroll
            for (int nb = 0; nb < 4; nb++) { mma_bf16(s[nb], ql[kk], bh[nb]); }
            #pragma unroll
            for (int nb = 0; nb < 4; nb++) { mma_bf16(s[nb], qh[kk], bl[nb]); }
        }

        float mx0 = -1e30f;
        float mx1 = -1e30f;
        #pragma unroll
        for (int nb = 0; nb < 4; nb++) {
            #pragma unroll
            for (int ii = 0; ii < 2; ii++) {
                int j = k0 + nb * 8 + t2 + ii;
                float v0 = (j <= gi0 && j >= gi0 - WSIZE) ? s[nb][ii] * sscale : -1e30f;
                float v1 = (j <= gi1 && j >= gi1 - WSIZE) ? s[nb][2 + ii] * sscale : -1e30f;
                s[nb][ii] = v0;
                s[nb][2 + ii] = v1;
                mx0 = fmaxf(mx0, v0);
                mx1 = fmaxf(mx1, v1);
            }
        }
        mx0 = fmaxf(mx0, __shfl_xor_sync(~0u, mx0, 1));
        mx0 = fmaxf(mx0, __shfl_xor_sync(~0u, mx0, 2));
        mx1 = fmaxf(mx1, __shfl_xor_sync(~0u, mx1, 1));
        mx1 = fmaxf(mx1, __shfl_xor_sync(~0u, mx1, 2));
        float mn0 = fmaxf(m0s, mx0);
        float mn1 = fmaxf(m1s, mx1);
        float a0 = __expf(m0s - mn0);
        float a1 = __expf(m1s - mn1);
        m0s = mn0;
        m1s = mn1;

        float su0 = 0.f;
        float su1 = 0.f;
        uint32_t ph[2][4];
        uint32_t pl[2][4];
        #pragma unroll
        for (int nb = 0; nb < 4; nb++) {
            float p0 = __expf(s[nb][0] - mn0);
            float p1 = __expf(s[nb][1] - mn0);
            float p2 = __expf(s[nb][2] - mn1);
            float p3 = __expf(s[nb][3] - mn1);
            su0 += p0 + p1;
            su1 += p2 + p3;
            int c = nb >> 1;
            int half = (nb & 1) << 1;
            uint32_t h01 = pack_bf16x2(p0, p1);
            uint32_t h23 = pack_bf16x2(p2, p3);
            ph[c][half]     = h01;
            ph[c][half + 1] = h23;
            __nv_bfloat162* hp01 = (__nv_bfloat162*)&h01;
            __nv_bfloat162* hp23 = (__nv_bfloat162*)&h23;
            pl[c][half]     = pack_bf16x2(p0 - __bfloat162float(hp01->x),
                                          p1 - __bfloat162float(hp01->y));
            pl[c][half + 1] = pack_bf16x2(p2 - __bfloat162float(hp23->x),
                                          p3 - __bfloat162float(hp23->y));
        }
        su0 += __shfl_xor_sync(~0u, su0, 1);
        su0 += __shfl_xor_sync(~0u, su0, 2);
        su1 += __shfl_xor_sync(~0u, su1, 1);
        su1 += __shfl_xor_sync(~0u, su1, 2);
        l0 = l0 * a0 + su0;
        l1 = l1 * a1 + su1;

        #pragma unroll
        for (int nf = 0; nf < 16; nf++) {
            o[nf][0] *= a0;
            o[nf][1] *= a0;
            o[nf][2] *= a1;
            o[nf][3] *= a1;
        }

        #pragma unroll
        for (int c = 0; c < 2; c++) {
            #pragma unroll
            for (int nb = 0; nb < 8; nb++) {
                uint32_t vh4[4], vl4[4];
                unsigned off = (unsigned)((c * 16 + l15) * KST + nb * 16 + l16o) * 2u;
                ldsm_x4_t(vh4, svh_b + off);
                ldsm_x4_t(vl4, svl_b + off);
                uint32_t b0h[2], b1h[2], b0l[2], b1l[2];
                b0h[0] = vh4[0]; b0h[1] = vh4[1];
                b1h[0] = vh4[2]; b1h[1] = vh4[3];
                b0l[0] = vl4[0]; b0l[1] = vl4[1];
                b1l[0] = vl4[2]; b1l[1] = vl4[3];
                // alternate accumulators between products
                mma_bf16(o[2 * nb],     ph[c], b0h);
                mma_bf16(o[2 * nb + 1], ph[c], b1h);
                mma_bf16(o[2 * nb],     pl[c], b0h);
                mma_bf16(o[2 * nb + 1], pl[c], b1h);
                mma_bf16(o[2 * nb],     ph[c], b0l);
                mma_bf16(o[2 * nb + 1], ph[c], b1l);
            }
        }
        buf ^= 1;
    }

    // ---- fused epilogue: out = y * silu(g) ----
    const float il0 = 1.0f / l0;
    const float il1 = 1.0f / l1;
    const int t0 = q0 + wm + g;
    const int t1 = t0 + 8;
    const size_t base0 = ((size_t)(b * T_SEQ + t0)) * D_MODEL + h * DH;
    const size_t base1 = ((size_t)(b * T_SEQ + t1)) * D_MODEL + h * DH;
    #pragma unroll
    for (int nf = 0; nf < 16; nf++) {
        int d = nf * 8 + t2;
        float2 gv0 = *(const float2*)(g_gmat + base0 + d);
        float2 gv1 = *(const float2*)(g_gmat + base1 + d);
        float y00 = o[nf][0] * il0;
        float y01 = o[nf][1] * il0;
        float y10 = o[nf][2] * il1;
        float y11 = o[nf][3] * il1;
        float2 r0;
        float2 r1;
        r0.x = y00 * gv0.x / (1.0f + expf(-gv0.x));
        r0.y = y01 * gv0.y / (1.0f + expf(-gv0.y));
        r1.x = y10 * gv1.x / (1.0f + expf(-gv1.x));
        r1.y = y11 * gv1.y / (1.0f + expf(-gv1.y));
        *(float2*)(out + base0 + d) = r0;
        *(float2*)(out + base1 + d) = r1;
    }
}

// ---------------- launch ----------------
extern "C" void kernel_launch(void* const* d_in, const int* in_sizes, int n_in,
                              void* d_out, int out_size) {
    const float* x      = (const float*)d_in[0];
    const float* Wqkv   = (const float*)d_in[1];
    const float* Wrk    = (const float*)d_in[2];
    const float* brk    = (const float*)d_in[3];
    const float* scaler = (const float*)d_in[4];
    const float* Wg     = (const float*)d_in[5];
    float* out = (float*)d_out;

    float* p_g;
    __nv_bfloat16* p_Ah;
    __nv_bfloat16* p_Al;
    __nv_bfloat16* p_Bqh;
    __nv_bfloat16* p_Bql;
    __nv_bfloat16* p_Bgh;
    __nv_bfloat16* p_Bgl;
    cudaGetSymbolAddress((void**)&p_g,   g_gmat);
    cudaGetSymbolAddress((void**)&p_Ah,  g_Ah);
    cudaGetSymbolAddress((void**)&p_Al,  g_Al);
    cudaGetSymbolAddress((void**)&p_Bqh, g_Bqh);
    cudaGetSymbolAddress((void**)&p_Bql, g_Bql);
    cudaGetSymbolAddress((void**)&p_Bgh, g_Bgh);
    cudaGetSymbolAddress((void**)&p_Bgl, g_Bgl);

    cudaFuncSetAttribute(gemm_bf16x3_dual,
                         cudaFuncAttributeMaxDynamicSharedMemorySize, GSMEM_BYTES);
    cudaFuncSetAttribute(attn_kernel,
                         cudaFuncAttributeMaxDynamicSharedMemorySize, ASMEM_BYTES);

    cvt_all<<<(CVT_N3 + 255) / 256, 256>>>(x, Wqkv, Wrk, Wg);

    gemm_bf16x3_dual<<<dim3(NB1 + NB2, BT / BM), 256, GSMEM_BYTES>>>(
        p_Ah, p_Al, p_Bqh, p_Bql, p_Bgh, p_Bgl, p_g, scaler, brk, D_MODEL);

    attn_kernel<<<dim3(T_SEQ / ATQ, NH, B_SZ), 256, ASMEM_BYTES>>>(out);
}